// round 2
// baseline (speedup 1.0000x reference)
#include <cuda_runtime.h>
#include <cuda_bf16.h>
#include <math.h>

// Problem constants (fixed by the dataset)
#define NN    50000
#define DEG   16
#define EDGES (NN * DEG)      // 800000
#define DIM   128
#define HID   128

// Persistent scratch: layer-1 node projections A = F @ W1[0:128], B = F @ W1[128:256]
__device__ float g_A[NN * DIM];
__device__ float g_B[NN * DIM];

// ---------------------------------------------------------------------------
// Kernel 1: AB = features[N,128] @ Wcat[128,256]  (Wcat col j<128 -> w1 rows 0..127,
// col j>=128 -> w1 rows 128..255). Tiled fp32 GEMM, TM=64, TN=64, 256 threads.
// ---------------------------------------------------------------------------
#define K1_SMEM_FLOATS (64 * 132 + 128 * 68)

__global__ void layer1_gemm_kernel(const float* __restrict__ feat,
                                   const float* __restrict__ w1) {
    extern __shared__ float smem1[];
    float* featS = smem1;              // [64][132]
    float* wS    = smem1 + 64 * 132;   // [128][68]

    const int tid = threadIdx.x;
    const int m0 = blockIdx.x * 64;
    const int n0 = blockIdx.y * 64;

    // Load feature tile [64][128]
    for (int t = tid; t < 64 * 32; t += 256) {
        int r = t >> 5, c4 = (t & 31) << 2;
        int gr = m0 + r;
        float4 v = make_float4(0.f, 0.f, 0.f, 0.f);
        if (gr < NN) v = *(const float4*)&feat[gr * DIM + c4];
        *(float4*)&featS[r * 132 + c4] = v;
    }
    // Load Wcat tile [128][64]
    for (int t = tid; t < 128 * 16; t += 256) {
        int k = t >> 4, c4 = (t & 15) << 2;
        int n = n0 + c4;
        const float* src = (n < 128) ? &w1[k * 128 + n]
                                     : &w1[(128 + k) * 128 + (n - 128)];
        *(float4*)&wS[k * 68 + c4] = *(const float4*)src;
    }
    __syncthreads();

    const int ty = tid >> 4, tx = tid & 15;
    const int r0 = ty * 4, c0 = tx * 4;
    float acc[4][4];
#pragma unroll
    for (int i = 0; i < 4; ++i)
#pragma unroll
        for (int j = 0; j < 4; ++j) acc[i][j] = 0.f;

#pragma unroll 4
    for (int k = 0; k < 128; ++k) {
        float a[4];
#pragma unroll
        for (int i = 0; i < 4; ++i) a[i] = featS[(r0 + i) * 132 + k];
        float4 bq = *(const float4*)&wS[k * 68 + c0];
        float b[4] = {bq.x, bq.y, bq.z, bq.w};
#pragma unroll
        for (int i = 0; i < 4; ++i)
#pragma unroll
            for (int j = 0; j < 4; ++j) acc[i][j] = fmaf(a[i], b[j], acc[i][j]);
    }

#pragma unroll
    for (int i = 0; i < 4; ++i) {
        int node = m0 + r0 + i;
        if (node >= NN) continue;
        int n = n0 + c0;
        float4 o = make_float4(acc[i][0], acc[i][1], acc[i][2], acc[i][3]);
        if (n < 128) *(float4*)&g_A[node * DIM + n] = o;
        else         *(float4*)&g_B[node * DIM + (n - 128)] = o;
    }
}

// ---------------------------------------------------------------------------
// Kernel 2: per-block = 8 nodes = 128 edges.
// ---------------------------------------------------------------------------
#define H1S 132
#define K2_SMEM_FLOATS (128 * H1S + 128 * H1S + 128 * 16 + 4 * 128)

__global__ void edge_mlp_mask_kernel(const int* __restrict__ colIdx,
                                     const float* __restrict__ values,
                                     const float* __restrict__ temperature,
                                     const float* __restrict__ w1,
                                     const float* __restrict__ b1,
                                     const float* __restrict__ w2,
                                     const float* __restrict__ b2,
                                     const float* __restrict__ w3,
                                     const float* __restrict__ b3,
                                     float* __restrict__ out) {
    extern __shared__ float smem[];
    float* h1T  = smem;                    // [128(j)][132(el)]
    float* w2s  = h1T + 128 * H1S;         // [128(k)][132(j)]
    float* zred = w2s + 128 * H1S;         // [128(el)][16(group)]
    float* b2s  = zred + 128 * 16;         // [128]
    float* w3s  = b2s + 128;               // [128]
    float* zz   = w3s + 128;               // [128]

    const int tid = threadIdx.x;
    const int base_node = blockIdx.x * 8;
    const int e0 = blockIdx.x * 128;

    // stage w2 + b2 + w3
    for (int t = tid; t < 128 * 32; t += 256) {
        int k = t >> 5, c4 = (t & 31) << 2;
        float4 v = *(const float4*)&w2[k * 128 + c4];
        *(float4*)&w2s[k * H1S + c4] = v;
    }
    if (tid < 128) {
        b2s[tid] = b2[tid];
        w3s[tid] = w3[tid];
    }

    // Phase 1: h1T[j][el] = relu(A[row] + B[col] + v*w1[256,j] + b1[j])
    {
        const int j = tid & 127;
        const int half = tid >> 7;
        const float b1j = b1[j];
        const float w1rj = w1[256 * 128 + j];
#pragma unroll
        for (int nn = 0; nn < 4; ++nn) {
            const int n = half * 4 + nn;
            const float a = g_A[(base_node + n) * DIM + j] + b1j;
#pragma unroll
            for (int t = 0; t < 16; ++t) {
                const int el = n * 16 + t;
                const int ge = e0 + el;
                const int c = colIdx[ge];
                const float v = values[ge];
                float h = fmaf(v, w1rj, a + g_B[c * DIM + j]);
                h1T[j * H1S + el] = fmaxf(h, 0.f);
            }
        }
    }
    __syncthreads();

    // Phase 2: h2 = relu(h1 @ w2 + b2); z-partials = h2 @ w3
    {
        const int er0 = (tid & 15) * 8;
        const int grp = tid >> 4;      // 0..15
        const int jc0 = grp * 8;
        float acc[8][8];
#pragma unroll
        for (int i = 0; i < 8; ++i)
#pragma unroll
            for (int j = 0; j < 8; ++j) acc[i][j] = 0.f;

#pragma unroll 2
        for (int k = 0; k < 128; ++k) {
            const float* hr = &h1T[k * H1S + er0];
            float4 a0 = *(const float4*)(hr);
            float4 a1 = *(const float4*)(hr + 4);
            const float* wr = &w2s[k * H1S + jc0];
            float4 c0 = *(const float4*)(wr);
            float4 c1 = *(const float4*)(wr + 4);
            float av[8] = {a0.x, a0.y, a0.z, a0.w, a1.x, a1.y, a1.z, a1.w};
            float bv[8] = {c0.x, c0.y, c0.z, c0.w, c1.x, c1.y, c1.z, c1.w};
#pragma unroll
            for (int i = 0; i < 8; ++i)
#pragma unroll
                for (int j = 0; j < 8; ++j)
                    acc[i][j] = fmaf(av[i], bv[j], acc[i][j]);
        }
#pragma unroll
        for (int i = 0; i < 8; ++i) {
            float s = 0.f;
#pragma unroll
            for (int j = 0; j < 8; ++j) {
                float h2v = fmaxf(acc[i][j] + b2s[jc0 + j], 0.f);
                s = fmaf(h2v, w3s[jc0 + j], s);
            }
            zred[(er0 + i) * 16 + grp] = s;
        }
    }
    __syncthreads();

    if (tid < 128) {
        float s = b3[0];
#pragma unroll
        for (int g = 0; g < 16; ++g) s += zred[tid * 16 + g];
        zz[tid] = s;
    }
    __syncthreads();

    // Phase 3: faithful f32 chain. Transcendentals in double -> rounded to f32
    // (correctly rounded, immune to fast-math); IEEE f32 div; sequential sums.
    {
        const unsigned FULL = 0xffffffffu;
        const int lane = tid & 31;
        const int l = lane & 15;
        const int wnode = tid >> 5;          // 0..7
        const int el = wnode * 16 + l;
        const float zv = zz[el];

        // softmax(z) over the 16-edge segment
        float m = zv;
#pragma unroll
        for (int o = 8; o >= 1; o >>= 1) m = fmaxf(m, __shfl_xor_sync(FULL, m, o, 16));
        float x1 = __fsub_rn(zv, m);
        float ev = (float)exp((double)x1);
        float s = 0.f;
#pragma unroll
        for (int o = 0; o < 16; ++o) s = __fadd_rn(s, __shfl_sync(FULL, ev, o, 16));
        float pi = __fdiv_rn(ev, s);

        // hard-concrete eval path: sigmoid(log(pi+eps)/T), clipped
        float larg = __fadd_rn(pi, 1e-8f);
        float lg = (float)log((double)larg);
        float sx = __fdiv_rn(lg, temperature[0]);
        float hard = (float)(1.0 / (1.0 + exp(-(double)sx)));
        hard = fminf(fmaxf(hard, 0.f), 1.f);

        // softmax(hard)
        float m2 = hard;
#pragma unroll
        for (int o = 8; o >= 1; o >>= 1) m2 = fmaxf(m2, __shfl_xor_sync(FULL, m2, o, 16));
        float x2 = __fsub_rn(hard, m2);
        float e2 = (float)exp((double)x2);
        float s2 = 0.f;
#pragma unroll
        for (int o = 0; o < 16; ++o) s2 = __fadd_rn(s2, __shfl_sync(FULL, e2, o, 16));
        float y = __fdiv_rn(e2, s2);

        // rank (descending, stable) -> 8th-largest value as threshold
        int r = 0;
#pragma unroll
        for (int o = 0; o < 16; ++o) {
            float yo = __shfl_sync(FULL, y, o, 16);
            r += (yo > y) || (yo == y && o < l);
        }
        unsigned bal = __ballot_sync(FULL, (r == 7) && (lane < 16));
        int src = __ffs(bal) - 1;
        float thre = __shfl_sync(FULL, y, src);

        // mask: f32 (y - thre) + 1e-7 > 0, exactly as reference
        float t = __fadd_rn(__fsub_rn(y, thre), 1e-7f);
        float outv = (t > 0.f) ? y : 0.f;
        if (lane < 16) out[e0 + el] = outv;
    }
}

// ---------------------------------------------------------------------------
extern "C" void kernel_launch(void* const* d_in, const int* in_sizes, int n_in,
                              void* d_out, int out_size) {
    const float* feat        = (const float*)d_in[0];
    const int*   indices     = (const int*)d_in[1];   // [2, E]
    const float* values      = (const float*)d_in[2]; // [E, 1]
    const float* temperature = (const float*)d_in[3];
    const float* w1          = (const float*)d_in[4]; // [257, 128]
    const float* b1          = (const float*)d_in[5];
    const float* w2          = (const float*)d_in[6]; // [128, 128]
    const float* b2          = (const float*)d_in[7];
    const float* w3          = (const float*)d_in[8]; // [128, 1]
    const float* b3          = (const float*)d_in[9];
    float* out = (float*)d_out;

    const int* colIdx = indices + EDGES;  // indices[1]

    const size_t smem1 = K1_SMEM_FLOATS * sizeof(float);
    const size_t smem2 = K2_SMEM_FLOATS * sizeof(float);
    cudaFuncSetAttribute(layer1_gemm_kernel,
                         cudaFuncAttributeMaxDynamicSharedMemorySize, (int)smem1);
    cudaFuncSetAttribute(edge_mlp_mask_kernel,
                         cudaFuncAttributeMaxDynamicSharedMemorySize, (int)smem2);

    dim3 g1((NN + 63) / 64, 2 * DIM / 64);  // 782 x 4
    layer1_gemm_kernel<<<g1, 256, smem1>>>(feat, w1);

    edge_mlp_mask_kernel<<<EDGES / 128, 256, smem2>>>(
        colIdx, values, temperature, w1, b1, w2, b2, w3, b3, out);
}